// round 15
// baseline (speedup 1.0000x reference)
#include <cuda_runtime.h>
#include <cuda_fp16.h>
#include <stdint.h>
#include <math.h>

#define BATCH 16
#define NQ 256
#define NKV 2304
#define HDIM 768
#define IMGD 1024
#define NHEADS 12
#define INTER 3072
#define HEADD 64
#define LN_EPS 1e-5f
#define ATT_SCALE 0.125f
#define LOG2E 1.44269504088896340736f

typedef __half f16;

// -------------------- scratch (device globals) ------------------------------
__device__ f16  g_xn[(size_t)BATCH * NKV * IMGD];
__device__ f16  g_hn[(size_t)BATCH * NQ * HDIM];
__device__ f16  g_q [(size_t)BATCH * NQ * HDIM];
__device__ f16  g_k [(size_t)BATCH * NKV * HDIM];
__device__ f16  g_vt[(size_t)BATCH * HDIM * NKV];
__device__ f16  g_ao[(size_t)BATCH * NQ * HDIM];
__device__ float g_o2[(size_t)BATCH * NQ * HDIM];
__device__ f16  g_hb[(size_t)BATCH * NQ * HDIM];
__device__ f16  g_t1[(size_t)BATCH * NQ * INTER];
// transposed weights [N][K]
__device__ f16  g_wq[HDIM * HDIM];
__device__ f16  g_wkv[(HDIM * 2) * IMGD];
__device__ f16  g_wo[HDIM * HDIM];
__device__ f16  g_w1[INTER * HDIM];
__device__ f16  g_w2[HDIM * INTER];

// -------------------- helpers ----------------------------------------------
__device__ __forceinline__ uint32_t smem_u32(const void* p) {
    uint32_t a;
    asm("{ .reg .u64 t; cvta.to.shared.u64 t, %1; cvt.u32.u64 %0, t; }" : "=r"(a) : "l"(p));
    return a;
}
__device__ __forceinline__ void ldmx4(uint32_t* r, uint32_t addr) {
    asm volatile("ldmatrix.sync.aligned.m8n8.x4.shared.b16 {%0,%1,%2,%3}, [%4];"
        : "=r"(r[0]), "=r"(r[1]), "=r"(r[2]), "=r"(r[3]) : "r"(addr));
}
__device__ __forceinline__ void mma16816(float* c, const uint32_t* a, const uint32_t* b) {
    asm volatile("mma.sync.aligned.m16n8k16.row.col.f32.f16.f16.f32 "
        "{%0,%1,%2,%3}, {%4,%5,%6,%7}, {%8,%9}, {%0,%1,%2,%3};"
        : "+f"(c[0]), "+f"(c[1]), "+f"(c[2]), "+f"(c[3])
        : "r"(a[0]), "r"(a[1]), "r"(a[2]), "r"(a[3]), "r"(b[0]), "r"(b[1]));
}
__device__ __forceinline__ uint32_t pack_h2(float a, float b) {
    __half2 h = __floats2half2_rn(a, b);
    return *(uint32_t*)&h;
}
__device__ __forceinline__ void cp16(uint32_t dst, const void* src) {
    asm volatile("cp.async.cg.shared.global [%0], [%1], 16;" :: "r"(dst), "l"(src));
}
#define CP_COMMIT() asm volatile("cp.async.commit_group;")
#define CP_WAIT0()  asm volatile("cp.async.wait_group 0;")
#define CP_WAIT1()  asm volatile("cp.async.wait_group 1;")

// ======================= fp16 MMA GEMM ======================================
// 128-thread CTA, tile 64x64. Warp tile 32x32 (4 warps: wm=wid&1, wn=wid>>1).
// BK=64 chunks (pitch 144B), 2-stage cp.async pipeline (R9 order).
// 6 CTAs/SM -> 24 warps, 6 independent barrier domains.
// EPI: 1 f16 (x+bias)*alpha; 2 kv-split; 4 fp32 x+bias+res; 5 f16 gelu(x+bias)
#define GPITCH 144
#define GTHREADS 128
#define GBM 64
#define GBN 64

template <int EPI>
__global__ void __launch_bounds__(GTHREADS, 6) mma_gemm(
    const f16* __restrict__ A, const f16* __restrict__ B,
    const float* __restrict__ bias, const float* __restrict__ res,
    float* __restrict__ Cf, f16* __restrict__ Ch, f16* __restrict__ C2h,
    int K, long long lda, long long ldb, long long ldc, float alpha)
{
    extern __shared__ char smem[];
    constexpr int BM  = GBM;
    constexpr int BN  = GBN;
    constexpr int MT  = 32;
    constexpr int NT  = 32;
    constexpr int MI  = 2;          // MT/16
    constexpr int NI2 = 2;          // NT/16
    constexpr int ASZ = BM * GPITCH;
    constexpr int BSZ = BN * GPITCH;
    constexpr int STG = ASZ + BSZ;

    const int tid = threadIdx.x, wid = tid >> 5, lane = tid & 31;
    const int wm = wid & 1, wn = wid >> 1;
    const long long bm = (long long)blockIdx.y * BM;
    const long long bn = (long long)blockIdx.x * BN;

    const f16* gA = A + bm * lda;
    const f16* gB = B + bn * ldb;

    float acc[MI][NI2 * 2][4];
#pragma unroll
    for (int i = 0; i < MI; i++)
#pragma unroll
        for (int j = 0; j < NI2 * 2; j++)
#pragma unroll
            for (int t = 0; t < 4; t++) acc[i][j][t] = 0.f;

    const uint32_t sb = smem_u32(smem);
    const int NC = K >> 6;

    auto fill = [&](int s, int c) {
        uint32_t base = sb + s * STG;
        const long long k0 = (long long)c * 64;
#pragma unroll
        for (int i = tid; i < BM * 8; i += GTHREADS) {
            int r = i >> 3, q = i & 7;
            cp16(base + r * GPITCH + q * 16, gA + r * lda + k0 + q * 8);
        }
#pragma unroll
        for (int i = tid; i < BN * 8; i += GTHREADS) {
            int r = i >> 3, q = i & 7;
            cp16(base + ASZ + r * GPITCH + q * 16, gB + r * ldb + k0 + q * 8);
        }
    };

    fill(0, 0);
    CP_COMMIT();
    CP_WAIT0();
    __syncthreads();

    const int a_r = (lane & 7) + ((lane >> 3) & 1) * 8;
    const int a_k = ((lane >> 4) & 1) * 8;
    const int b_r = (lane & 7) + ((lane >> 4) & 1) * 8;
    const int b_k = ((lane >> 3) & 1) * 8;

    for (int c = 0; c < NC; c++) {
        if (c + 1 < NC) { fill((c + 1) & 1, c + 1); CP_COMMIT(); }
        const uint32_t aH = sb + (c & 1) * STG;
        const uint32_t bH = aH + ASZ;
#pragma unroll
        for (int kk = 0; kk < 64; kk += 16) {
            uint32_t af[MI][4];
#pragma unroll
            for (int mi = 0; mi < MI; mi++) {
                uint32_t off = (uint32_t)(wm * MT + mi * 16 + a_r) * GPITCH + (kk + a_k) * 2;
                ldmx4(af[mi], aH + off);
            }
#pragma unroll
            for (int nj = 0; nj < NI2; nj++) {
                uint32_t bf[4];
                uint32_t off = (uint32_t)(wn * NT + nj * 16 + b_r) * GPITCH + (kk + b_k) * 2;
                ldmx4(bf, bH + off);
#pragma unroll
                for (int mi = 0; mi < MI; mi++) {
                    mma16816(acc[mi][nj * 2 + 0], af[mi], bf + 0);
                    mma16816(acc[mi][nj * 2 + 1], af[mi], bf + 2);
                }
            }
        }
        CP_WAIT0();
        __syncthreads();
    }

    // ---- stage C into smem fp32 tile ----
    constexpr int P2 = BN + 4;
    float* tile = (float*)smem;
#pragma unroll
    for (int mi = 0; mi < MI; mi++)
#pragma unroll
        for (int j = 0; j < NI2 * 2; j++) {
            int row = wm * MT + mi * 16 + (lane >> 2);
            int col = wn * NT + j * 8 + (lane & 3) * 2;
            tile[row * P2 + col]           = acc[mi][j][0];
            tile[row * P2 + col + 1]       = acc[mi][j][1];
            tile[(row + 8) * P2 + col]     = acc[mi][j][2];
            tile[(row + 8) * P2 + col + 1] = acc[mi][j][3];
        }
    __syncthreads();

    if (EPI == 2 && bn >= 768) {
        for (int idx = tid; idx < BM * BN; idx += GTHREADS) {
            int rr = idx & (BM - 1), cc = idx >> 6;
            long long grow = bm + rr;
            long long vcol = bn + cc - 768;
            float val = tile[rr * P2 + cc] + res[vcol];
            long long b = grow / NKV, t = grow - b * NKV;
            C2h[(b * HDIM + vcol) * NKV + t] = __float2half_rn(val);
        }
        return;
    }
    for (int idx = tid; idx < BM * BN; idx += GTHREADS) {
        int rr = idx / BN, cc = idx % BN;
        long long grow = bm + rr, gcol = bn + cc;
        float val = tile[rr * P2 + cc];
        if (EPI == 1) {
            Ch[grow * ldc + gcol] = __float2half_rn((val + bias[gcol]) * alpha);
        } else if (EPI == 2) {
            Ch[grow * (long long)HDIM + gcol] = __float2half_rn(val + bias[gcol]);
        } else if (EPI == 4) {
            Cf[grow * ldc + gcol] = val + bias[gcol] + res[grow * ldc + gcol];
        } else if (EPI == 5) {
            float u = val + bias[gcol];
            Ch[grow * ldc + gcol] =
                __float2half_rn(0.5f * u * (1.f + erff(u * 0.70710678118654752f)));
        }
    }
}

// ======================= fused flash attention ==============================
// grid (NQ/128, BATCH*NHEADS), 256 threads. q pre-scaled by ATT_SCALE*log2e;
// softmax uses exp2. 2-stage cp.async K/V pipeline. (R6-identical)
#define QK_PITCH 144
#define V_PITCH  272
#define KBLK_SZ (128 * QK_PITCH)
#define VBLK_SZ (64 * V_PITCH)
#define FA_SMEM (128 * QK_PITCH + 2 * KBLK_SZ + 2 * VBLK_SZ)

__global__ void __launch_bounds__(256) flash_attn(
    const f16* __restrict__ q, const f16* __restrict__ k,
    const f16* __restrict__ vt, f16* __restrict__ ao)
{
    extern __shared__ char smem[];
    const uint32_t qbase = smem_u32(smem);
    const uint32_t kbase0 = qbase + 128 * QK_PITCH;
    const uint32_t vbase0 = kbase0 + 2 * KBLK_SZ;

    const int tid = threadIdx.x, lane = tid & 31, w = tid >> 5;
    const int z = blockIdx.y;
    const int b = z / NHEADS, h = z % NHEADS;
    const long long bm = (long long)blockIdx.x * 128;

    const f16* gQ = q + ((long long)b * NQ + bm) * HDIM + h * 64;
    const f16* gK = k + (long long)b * NKV * HDIM + h * 64;
    const f16* gV = vt + ((long long)b * HDIM + h * 64) * NKV;

    constexpr int NB = NKV / 128;  // 18

    auto fillKV = [&](int jb) {
        const int s = jb & 1;
        const f16* gKb = gK + (long long)jb * 128 * HDIM;
        uint32_t kb = kbase0 + s * KBLK_SZ;
#pragma unroll
        for (int i = tid; i < 128 * 8; i += 256) {
            int r = i >> 3, c = i & 7;
            cp16(kb + r * QK_PITCH + c * 16, gKb + (long long)r * HDIM + c * 8);
        }
        const f16* gVb = gV + jb * 128;
        uint32_t vb = vbase0 + s * VBLK_SZ;
#pragma unroll
        for (int i = tid; i < 64 * 16; i += 256) {
            int r = i >> 4, c = i & 15;
            cp16(vb + r * V_PITCH + c * 16, gVb + (long long)r * NKV + c * 8);
        }
    };

    for (int i = tid; i < 128 * 8; i += 256) {
        int r = i >> 3, c = i & 7;
        cp16(qbase + r * QK_PITCH + c * 16, gQ + (long long)r * HDIM + c * 8);
    }
    fillKV(0);
    CP_COMMIT();
    fillKV(1);
    CP_COMMIT();
    CP_WAIT1();
    __syncthreads();

    const int a_r = (lane & 7) + ((lane >> 3) & 1) * 8;
    const int a_k = ((lane >> 4) & 1) * 8;
    const int b_r = (lane & 7) + ((lane >> 4) & 1) * 8;
    const int b_k = ((lane >> 3) & 1) * 8;

    uint32_t qf[4][4];
#pragma unroll
    for (int s = 0; s < 4; s++)
        ldmx4(qf[s], qbase + (uint32_t)(16 * w + a_r) * QK_PITCH + (16 * s + a_k) * 2);

    float o[8][4];
#pragma unroll
    for (int i = 0; i < 8; i++)
#pragma unroll
        for (int t = 0; t < 4; t++) o[i][t] = 0.f;
    float m0 = -1e30f, m1 = -1e30f, l0 = 0.f, l1 = 0.f;

    for (int jb = 0; jb < NB; jb++) {
        if (jb > 0) {
            if (jb + 1 < NB) CP_WAIT1(); else CP_WAIT0();
            __syncthreads();
        }
        const uint32_t kb = kbase0 + (jb & 1) * KBLK_SZ;
        const uint32_t vb = vbase0 + (jb & 1) * VBLK_SZ;

        float sacc[16][4];
#pragma unroll
        for (int i = 0; i < 16; i++)
#pragma unroll
            for (int t = 0; t < 4; t++) sacc[i][t] = 0.f;
#pragma unroll
        for (int s = 0; s < 4; s++) {
#pragma unroll
            for (int np = 0; np < 8; np++) {
                uint32_t bf[4];
                ldmx4(bf, kb + (uint32_t)(16 * np + b_r) * QK_PITCH + (16 * s + b_k) * 2);
                mma16816(sacc[2 * np + 0], qf[s], bf + 0);
                mma16816(sacc[2 * np + 1], qf[s], bf + 2);
            }
        }

        float rm0 = -1e30f, rm1 = -1e30f;
#pragma unroll
        for (int i = 0; i < 16; i++) {
            rm0 = fmaxf(rm0, fmaxf(sacc[i][0], sacc[i][1]));
            rm1 = fmaxf(rm1, fmaxf(sacc[i][2], sacc[i][3]));
        }
        rm0 = fmaxf(rm0, __shfl_xor_sync(0xffffffffu, rm0, 1));
        rm0 = fmaxf(rm0, __shfl_xor_sync(0xffffffffu, rm0, 2));
        rm1 = fmaxf(rm1, __shfl_xor_sync(0xffffffffu, rm1, 1));
        rm1 = fmaxf(rm1, __shfl_xor_sync(0xffffffffu, rm1, 2));
        float mn0 = fmaxf(m0, rm0), mn1 = fmaxf(m1, rm1);
        float sc0 = exp2f(m0 - mn0), sc1 = exp2f(m1 - mn1);

        uint32_t pf[16][2];
        float rs0 = 0.f, rs1 = 0.f;
#pragma unroll
        for (int i = 0; i < 16; i++) {
            float e0 = exp2f(sacc[i][0] - mn0);
            float e1 = exp2f(sacc[i][1] - mn0);
            float e2 = exp2f(sacc[i][2] - mn1);
            float e3 = exp2f(sacc[i][3] - mn1);
            rs0 += e0 + e1; rs1 += e2 + e3;
            pf[i][0] = pack_h2(e0, e1);
            pf[i][1] = pack_h2(e2, e3);
        }
        rs0 += __shfl_xor_sync(0xffffffffu, rs0, 1);
        rs0 += __shfl_xor_sync(0xffffffffu, rs0, 2);
        rs1 += __shfl_xor_sync(0xffffffffu, rs1, 1);
        rs1 += __shfl_xor_sync(0xffffffffu, rs1, 2);
        l0 = l0 * sc0 + rs0;
        l1 = l1 * sc1 + rs1;
        m0 = mn0; m1 = mn1;

#pragma unroll
        for (int i = 0; i < 8; i++) {
            o[i][0] *= sc0; o[i][1] *= sc0;
            o[i][2] *= sc1; o[i][3] *= sc1;
        }

#pragma unroll
        for (int s = 0; s < 8; s++) {
            uint32_t af[4] = { pf[2 * s][0], pf[2 * s][1], pf[2 * s + 1][0], pf[2 * s + 1][1] };
#pragma unroll
            for (int np = 0; np < 4; np++) {
                uint32_t bf[4];
                ldmx4(bf, vb + (uint32_t)(16 * np + b_r) * V_PITCH + (16 * s + b_k) * 2);
                mma16816(o[2 * np + 0], af, bf + 0);
                mma16816(o[2 * np + 1], af, bf + 2);
            }
        }
        __syncthreads();
        if (jb + 2 < NB) { fillKV(jb + 2); CP_COMMIT(); }
    }

    float il0 = 1.f / l0, il1 = 1.f / l1;
    const int r = lane >> 2, t2 = (lane & 3) * 2;
    f16* gO = ao + ((long long)b * NQ + bm + 16 * w) * HDIM + h * 64;
#pragma unroll
    for (int nj = 0; nj < 8; nj++) {
        int col = 8 * nj + t2;
        *(uint32_t*)(gO + (long long)r * HDIM + col) =
            pack_h2(o[nj][0] * il0, o[nj][1] * il0);
        *(uint32_t*)(gO + (long long)(r + 8) * HDIM + col) =
            pack_h2(o[nj][2] * il1, o[nj][3] * il1);
    }
}

// -------------------- merged weight transpose + fp16 ------------------------
struct WJobs {
    const float* W[6];
    f16* T[6];
    int N[6], nbx[6], rowOff[6], ldT[6];
    int base[7];
};

__global__ void __launch_bounds__(256) wprep_all(WJobs jb)
{
    __shared__ float s[32][33];
    int bid = blockIdx.x;
    int j = 0;
#pragma unroll
    for (int i = 1; i < 6; i++) if (bid >= jb.base[i]) j = i;
    int lb = bid - jb.base[j];
    const float* W = jb.W[j];
    const int N = jb.N[j];
    int n0 = (lb % jb.nbx[j]) * 32, k0 = (lb / jb.nbx[j]) * 32;
    int tx = threadIdx.x & 31, ty = threadIdx.x >> 5;
#pragma unroll
    for (int jj = 0; jj < 4; jj++)
        s[ty + jj * 8][tx] = W[(long long)(k0 + ty + jj * 8) * N + n0 + tx];
    __syncthreads();
    f16* T = jb.T[j];
    const int ldT = jb.ldT[j], rowOff = jb.rowOff[j];
#pragma unroll
    for (int jj = 0; jj < 4; jj++) {
        int n = n0 + ty + jj * 8, kx = k0 + tx;
        T[(long long)(n + rowOff) * ldT + kx] = __float2half_rn(s[tx][ty + jj * 8]);
    }
}

// -------------------- LayerNorm -> fp16 --------------------------------------
template <int COLS>
__global__ void __launch_bounds__(256) ln_kernel(
    const float* __restrict__ x, const float* __restrict__ g,
    const float* __restrict__ b, f16* __restrict__ y)
{
    constexpr int PT = COLS / 256;
    const long long row = blockIdx.x;
    const float* xr = x + row * COLS;

    float v[PT];
    float s = 0.f, s2 = 0.f;
#pragma unroll
    for (int i = 0; i < PT; i++) {
        float t = xr[threadIdx.x + i * 256];
        v[i] = t; s += t; s2 += t * t;
    }
    __shared__ float red0[8], red1[8];
#pragma unroll
    for (int o = 16; o; o >>= 1) {
        s  += __shfl_xor_sync(0xffffffffu, s, o);
        s2 += __shfl_xor_sync(0xffffffffu, s2, o);
    }
    int w = threadIdx.x >> 5, l = threadIdx.x & 31;
    if (l == 0) { red0[w] = s; red1[w] = s2; }
    __syncthreads();
    s  = red0[0] + red0[1] + red0[2] + red0[3] + red0[4] + red0[5] + red0[6] + red0[7];
    s2 = red1[0] + red1[1] + red1[2] + red1[3] + red1[4] + red1[5] + red1[6] + red1[7];

    float mu  = s * (1.f / COLS);
    float var = s2 * (1.f / COLS) - mu * mu;
    float inv = rsqrtf(var + LN_EPS);
#pragma unroll
    for (int i = 0; i < PT; i++) {
        int c = threadIdx.x + i * 256;
        y[row * COLS + c] = __float2half_rn((v[i] - mu) * inv * g[c] + b[c]);
    }
}

// -------------------- launch ------------------------------------------------
#define SMEM_GEMM ((2 * (GBM + GBN) * GPITCH) > (GBM * (GBN + 4) * 4) ? \
                   (2 * (GBM + GBN) * GPITCH) : (GBM * (GBN + 4) * 4))

extern "C" void kernel_launch(void* const* d_in, const int* in_sizes, int n_in,
                              void* d_out, int out_size)
{
    const float* hs   = (const float*)d_in[0];
    const float* x    = (const float*)d_in[1];
    const float* Wq   = (const float*)d_in[2];
    const float* bq   = (const float*)d_in[3];
    const float* Wk   = (const float*)d_in[4];
    const float* bk   = (const float*)d_in[5];
    const float* Wv   = (const float*)d_in[6];
    const float* bv   = (const float*)d_in[7];
    const float* Wo   = (const float*)d_in[8];
    const float* bo   = (const float*)d_in[9];
    const float* W1   = (const float*)d_in[10];
    const float* b1   = (const float*)d_in[11];
    const float* W2   = (const float*)d_in[12];
    const float* b2   = (const float*)d_in[13];
    const float* gimg = (const float*)d_in[14];
    const float* bimg = (const float*)d_in[15];
    const float* ghid = (const float*)d_in[16];
    const float* bhid = (const float*)d_in[17];
    const float* gffn = (const float*)d_in[18];
    const float* bffn = (const float*)d_in[19];
    float* out = (float*)d_out;

    f16 *xn, *hn, *q, *k, *vt, *ao, *hb, *t1;
    f16 *wq, *wkv, *wo, *w1, *w2;
    float *o2;
    cudaGetSymbolAddress((void**)&xn, g_xn);
    cudaGetSymbolAddress((void**)&hn, g_hn);
    cudaGetSymbolAddress((void**)&q,  g_q);
    cudaGetSymbolAddress((void**)&k,  g_k);
    cudaGetSymbolAddress((void**)&vt, g_vt);
    cudaGetSymbolAddress((void**)&ao, g_ao);
    cudaGetSymbolAddress((void**)&o2, g_o2);
    cudaGetSymbolAddress((void**)&hb, g_hb);
    cudaGetSymbolAddress((void**)&t1, g_t1);
    cudaGetSymbolAddress((void**)&wq, g_wq);
    cudaGetSymbolAddress((void**)&wkv, g_wkv);
    cudaGetSymbolAddress((void**)&wo, g_wo);
    cudaGetSymbolAddress((void**)&w1, g_w1);
    cudaGetSymbolAddress((void**)&w2, g_w2);

    const int SG = SMEM_GEMM;
    cudaFuncSetAttribute(mma_gemm<1>, cudaFuncAttributeMaxDynamicSharedMemorySize, SG);
    cudaFuncSetAttribute(mma_gemm<2>, cudaFuncAttributeMaxDynamicSharedMemorySize, SG);
    cudaFuncSetAttribute(mma_gemm<4>, cudaFuncAttributeMaxDynamicSharedMemorySize, SG);
    cudaFuncSetAttribute(mma_gemm<5>, cudaFuncAttributeMaxDynamicSharedMemorySize, SG);
    cudaFuncSetAttribute(flash_attn, cudaFuncAttributeMaxDynamicSharedMemorySize, FA_SMEM);

    const int MQ = BATCH * NQ;    // 4096
    const int MK = BATCH * NKV;   // 36864

    // 0) merged weight prep
    {
        WJobs jb;
        const float* Ws[6] = { Wq, Wk, Wv, Wo, W1, W2 };
        f16* Ts[6]         = { wq, wkv, wkv, wo, w1, w2 };
        int Ns[6]          = { HDIM, HDIM, HDIM, HDIM, INTER, HDIM };
        int Ks[6]          = { HDIM, IMGD, IMGD, HDIM, HDIM, INTER };
        int ro[6]          = { 0, 0, HDIM, 0, 0, 0 };
        int lt[6]          = { HDIM, IMGD, IMGD, HDIM, HDIM, INTER };
        int total = 0;
        for (int i = 0; i < 6; i++) {
            jb.W[i] = Ws[i]; jb.T[i] = Ts[i]; jb.N[i] = Ns[i];
            jb.nbx[i] = Ns[i] / 32; jb.rowOff[i] = ro[i]; jb.ldT[i] = lt[i];
            jb.base[i] = total;
            total += (Ns[i] / 32) * (Ks[i] / 32);
        }
        jb.base[6] = total;
        wprep_all<<<total, 256>>>(jb);
    }

    // 1) LayerNorms -> fp16
    ln_kernel<IMGD><<<BATCH * NKV, 256>>>(x, gimg, bimg, xn);
    ln_kernel<HDIM><<<BATCH * NQ, 256>>>(hs, ghid, bhid, hn);

    // 2) q = (hn @ Wq + bq) * SCALE * log2e   (exp2-domain softmax)
    mma_gemm<1><<<dim3(HDIM / GBN, MQ / GBM), GTHREADS, SG>>>(
        hn, wq, bq, nullptr, nullptr, q, nullptr,
        HDIM, HDIM, HDIM, HDIM, ATT_SCALE * LOG2E);

    // 3) [k|v] = xn @ [Wk|Wv] + [bk|bv]  -> k + v_t
    mma_gemm<2><<<dim3((2 * HDIM) / GBN, MK / GBM), GTHREADS, SG>>>(
        xn, wkv, bk, bv, nullptr, k, vt,
        IMGD, IMGD, IMGD, HDIM, 1.f);

    // 4) fused attention: ao = softmax(q k^T) v
    flash_attn<<<dim3(NQ / 128, BATCH * NHEADS), 256, FA_SMEM>>>(q, k, vt, ao);

    // 5) o2 = ao @ Wo + bo + hidden_states  -> fp32
    mma_gemm<4><<<dim3(HDIM / GBN, MQ / GBM), GTHREADS, SG>>>(
        ao, wo, bo, hs, o2, nullptr, nullptr,
        HDIM, HDIM, HDIM, HDIM, 1.f);

    // 6) hb = LN(o2)
    ln_kernel<HDIM><<<BATCH * NQ, 256>>>(o2, gffn, bffn, hb);

    // 7) t1 = gelu(hb @ W1 + b1)
    mma_gemm<5><<<dim3(INTER / GBN, MQ / GBM), GTHREADS, SG>>>(
        hb, w1, b1, nullptr, nullptr, t1, nullptr,
        HDIM, HDIM, HDIM, INTER, 1.f);

    // 8) out = t1 @ W2 + b2 + o2  -> fp32
    mma_gemm<4><<<dim3(HDIM / GBN, MQ / GBM), GTHREADS, SG>>>(
        t1, w2, b2, o2, out, nullptr, nullptr,
        INTER, INTER, INTER, HDIM, 1.f);
}

// round 16
// speedup vs baseline: 1.0816x; 1.0816x over previous
#include <cuda_runtime.h>
#include <cuda_fp16.h>
#include <stdint.h>
#include <math.h>

#define BATCH 16
#define NQ 256
#define NKV 2304
#define HDIM 768
#define IMGD 1024
#define NHEADS 12
#define INTER 3072
#define HEADD 64
#define LN_EPS 1e-5f
#define ATT_SCALE 0.125f
#define LOG2E 1.44269504088896340736f

typedef __half f16;

// -------------------- scratch (device globals) ------------------------------
__device__ f16  g_xn[(size_t)BATCH * NKV * IMGD];
__device__ f16  g_hn[(size_t)BATCH * NQ * HDIM];
__device__ f16  g_q [(size_t)BATCH * NQ * HDIM];
__device__ f16  g_k [(size_t)BATCH * NKV * HDIM];
__device__ f16  g_vt[(size_t)BATCH * HDIM * NKV];
__device__ f16  g_ao[(size_t)BATCH * NQ * HDIM];
__device__ float g_o2[(size_t)BATCH * NQ * HDIM];
__device__ f16  g_hb[(size_t)BATCH * NQ * HDIM];
__device__ f16  g_t1[(size_t)BATCH * NQ * INTER];
// transposed weights [N][K]
__device__ f16  g_wq[HDIM * HDIM];
__device__ f16  g_wkv[(HDIM * 2) * IMGD];
__device__ f16  g_wo[HDIM * HDIM];
__device__ f16  g_w1[INTER * HDIM];
__device__ f16  g_w2[HDIM * INTER];

// -------------------- helpers ----------------------------------------------
__device__ __forceinline__ uint32_t smem_u32(const void* p) {
    uint32_t a;
    asm("{ .reg .u64 t; cvta.to.shared.u64 t, %1; cvt.u32.u64 %0, t; }" : "=r"(a) : "l"(p));
    return a;
}
__device__ __forceinline__ void ldmx4(uint32_t* r, uint32_t addr) {
    asm volatile("ldmatrix.sync.aligned.m8n8.x4.shared.b16 {%0,%1,%2,%3}, [%4];"
        : "=r"(r[0]), "=r"(r[1]), "=r"(r[2]), "=r"(r[3]) : "r"(addr));
}
__device__ __forceinline__ void mma16816(float* c, const uint32_t* a, const uint32_t* b) {
    asm volatile("mma.sync.aligned.m16n8k16.row.col.f32.f16.f16.f32 "
        "{%0,%1,%2,%3}, {%4,%5,%6,%7}, {%8,%9}, {%0,%1,%2,%3};"
        : "+f"(c[0]), "+f"(c[1]), "+f"(c[2]), "+f"(c[3])
        : "r"(a[0]), "r"(a[1]), "r"(a[2]), "r"(a[3]), "r"(b[0]), "r"(b[1]));
}
__device__ __forceinline__ uint32_t pack_h2(float a, float b) {
    __half2 h = __floats2half2_rn(a, b);
    return *(uint32_t*)&h;
}
__device__ __forceinline__ void cp16(uint32_t dst, const void* src) {
    asm volatile("cp.async.cg.shared.global [%0], [%1], 16;" :: "r"(dst), "l"(src));
}
#define CP_COMMIT() asm volatile("cp.async.commit_group;")
#define CP_WAIT0()  asm volatile("cp.async.wait_group 0;")
#define CP_WAIT1()  asm volatile("cp.async.wait_group 1;")

// ======================= fp16 MMA GEMM (R11 config) =========================
// 128-thread CTA, tile 128x64. Warp tile 64x32 (wm=wid&1, wn=wid>>1).
// BK=64 chunks (pitch 144B), 2-stage cp.async pipeline (R9 order). 4 CTAs/SM.
#define GPITCH 144
#define GTHREADS 128
#define GBN 64

// EPI: 4 fp32 x+bias+res; 5 f16 gelu(x+bias)
template <int EPI>
__global__ void __launch_bounds__(GTHREADS, 4) mma_gemm(
    const f16* __restrict__ A, const f16* __restrict__ B,
    const float* __restrict__ bias, const float* __restrict__ res,
    float* __restrict__ Cf, f16* __restrict__ Ch,
    int K, long long lda, long long ldb, long long ldc)
{
    extern __shared__ char smem[];
    constexpr int BN  = GBN;
    constexpr int MT  = 64;
    constexpr int NT  = 32;
    constexpr int MI  = 4;
    constexpr int NI2 = 2;
    constexpr int ASZ = 128 * GPITCH;
    constexpr int BSZ = BN * GPITCH;
    constexpr int STG = ASZ + BSZ;

    const int tid = threadIdx.x, wid = tid >> 5, lane = tid & 31;
    const int wm = wid & 1, wn = wid >> 1;
    const long long bm = (long long)blockIdx.y * 128;
    const long long bn = (long long)blockIdx.x * BN;

    const f16* gA = A + bm * lda;
    const f16* gB = B + bn * ldb;

    float acc[MI][NI2 * 2][4];
#pragma unroll
    for (int i = 0; i < MI; i++)
#pragma unroll
        for (int j = 0; j < NI2 * 2; j++)
#pragma unroll
            for (int t = 0; t < 4; t++) acc[i][j][t] = 0.f;

    const uint32_t sb = smem_u32(smem);
    const int NC = K >> 6;

    auto fill = [&](int s, int c) {
        uint32_t base = sb + s * STG;
        const long long k0 = (long long)c * 64;
#pragma unroll
        for (int i = tid; i < 128 * 8; i += GTHREADS) {
            int r = i >> 3, q = i & 7;
            cp16(base + r * GPITCH + q * 16, gA + r * lda + k0 + q * 8);
        }
#pragma unroll
        for (int i = tid; i < BN * 8; i += GTHREADS) {
            int r = i >> 3, q = i & 7;
            cp16(base + ASZ + r * GPITCH + q * 16, gB + r * ldb + k0 + q * 8);
        }
    };

    fill(0, 0);
    CP_COMMIT();
    CP_WAIT0();
    __syncthreads();

    const int a_r = (lane & 7) + ((lane >> 3) & 1) * 8;
    const int a_k = ((lane >> 4) & 1) * 8;
    const int b_r = (lane & 7) + ((lane >> 4) & 1) * 8;
    const int b_k = ((lane >> 3) & 1) * 8;

    for (int c = 0; c < NC; c++) {
        if (c + 1 < NC) { fill((c + 1) & 1, c + 1); CP_COMMIT(); }
        const uint32_t aH = sb + (c & 1) * STG;
        const uint32_t bH = aH + ASZ;
#pragma unroll
        for (int kk = 0; kk < 64; kk += 16) {
            uint32_t af[MI][4];
#pragma unroll
            for (int mi = 0; mi < MI; mi++) {
                uint32_t off = (uint32_t)(wm * MT + mi * 16 + a_r) * GPITCH + (kk + a_k) * 2;
                ldmx4(af[mi], aH + off);
            }
#pragma unroll
            for (int nj = 0; nj < NI2; nj++) {
                uint32_t bf[4];
                uint32_t off = (uint32_t)(wn * NT + nj * 16 + b_r) * GPITCH + (kk + b_k) * 2;
                ldmx4(bf, bH + off);
#pragma unroll
                for (int mi = 0; mi < MI; mi++) {
                    mma16816(acc[mi][nj * 2 + 0], af[mi], bf + 0);
                    mma16816(acc[mi][nj * 2 + 1], af[mi], bf + 2);
                }
            }
        }
        CP_WAIT0();
        __syncthreads();
    }

    constexpr int P2 = BN + 4;
    float* tile = (float*)smem;
#pragma unroll
    for (int mi = 0; mi < MI; mi++)
#pragma unroll
        for (int j = 0; j < NI2 * 2; j++) {
            int row = wm * MT + mi * 16 + (lane >> 2);
            int col = wn * NT + j * 8 + (lane & 3) * 2;
            tile[row * P2 + col]           = acc[mi][j][0];
            tile[row * P2 + col + 1]       = acc[mi][j][1];
            tile[(row + 8) * P2 + col]     = acc[mi][j][2];
            tile[(row + 8) * P2 + col + 1] = acc[mi][j][3];
        }
    __syncthreads();

    for (int idx = tid; idx < 128 * BN; idx += GTHREADS) {
        int rr = idx / BN, cc = idx % BN;
        long long grow = bm + rr, gcol = bn + cc;
        float val = tile[rr * P2 + cc];
        if (EPI == 4) {
            Cf[grow * ldc + gcol] = val + bias[gcol] + res[grow * ldc + gcol];
        } else if (EPI == 5) {
            float u = val + bias[gcol];
            Ch[grow * ldc + gcol] =
                __float2half_rn(0.5f * u * (1.f + erff(u * 0.70710678118654752f)));
        }
    }
}

// ======================= merged Q + KV projection ===========================
// grid (24, 320): y<288 -> KV rows (A=xn, B=wkv, K=1024); y>=288 -> Q rows
// (A=hn, B=wq, K=768; only x<12 active). Same R11 mainloop.
#define KV_YBLKS 288   // MK/128

__global__ void __launch_bounds__(GTHREADS, 4) qkv_gemm(
    const f16* __restrict__ xn, const f16* __restrict__ wkv,
    const float* __restrict__ bk, const float* __restrict__ bv,
    f16* __restrict__ kout, f16* __restrict__ vt,
    const f16* __restrict__ hn, const f16* __restrict__ wq,
    const float* __restrict__ bq, f16* __restrict__ qout, float alphaQ)
{
    extern __shared__ char smem[];
    constexpr int BN  = GBN;
    constexpr int MT  = 64;
    constexpr int NT  = 32;
    constexpr int MI  = 4;
    constexpr int NI2 = 2;
    constexpr int ASZ = 128 * GPITCH;
    constexpr int BSZ = BN * GPITCH;
    constexpr int STG = ASZ + BSZ;

    const bool isQ = blockIdx.y >= KV_YBLKS;
    if (isQ && blockIdx.x >= HDIM / GBN) return;

    const int tid = threadIdx.x, wid = tid >> 5, lane = tid & 31;
    const int wm = wid & 1, wn = wid >> 1;
    const long long bm = (long long)(isQ ? blockIdx.y - KV_YBLKS : blockIdx.y) * 128;
    const long long bn = (long long)blockIdx.x * BN;

    const int K = isQ ? HDIM : IMGD;
    const long long lda = K, ldb = K;
    const f16* gA = (isQ ? hn : xn) + bm * lda;
    const f16* gB = (isQ ? wq : wkv) + bn * ldb;

    float acc[MI][NI2 * 2][4];
#pragma unroll
    for (int i = 0; i < MI; i++)
#pragma unroll
        for (int j = 0; j < NI2 * 2; j++)
#pragma unroll
            for (int t = 0; t < 4; t++) acc[i][j][t] = 0.f;

    const uint32_t sb = smem_u32(smem);
    const int NC = K >> 6;

    auto fill = [&](int s, int c) {
        uint32_t base = sb + s * STG;
        const long long k0 = (long long)c * 64;
#pragma unroll
        for (int i = tid; i < 128 * 8; i += GTHREADS) {
            int r = i >> 3, q = i & 7;
            cp16(base + r * GPITCH + q * 16, gA + r * lda + k0 + q * 8);
        }
#pragma unroll
        for (int i = tid; i < BN * 8; i += GTHREADS) {
            int r = i >> 3, q = i & 7;
            cp16(base + ASZ + r * GPITCH + q * 16, gB + r * ldb + k0 + q * 8);
        }
    };

    fill(0, 0);
    CP_COMMIT();
    CP_WAIT0();
    __syncthreads();

    const int a_r = (lane & 7) + ((lane >> 3) & 1) * 8;
    const int a_k = ((lane >> 4) & 1) * 8;
    const int b_r = (lane & 7) + ((lane >> 4) & 1) * 8;
    const int b_k = ((lane >> 3) & 1) * 8;

    for (int c = 0; c < NC; c++) {
        if (c + 1 < NC) { fill((c + 1) & 1, c + 1); CP_COMMIT(); }
        const uint32_t aH = sb + (c & 1) * STG;
        const uint32_t bH = aH + ASZ;
#pragma unroll
        for (int kk = 0; kk < 64; kk += 16) {
            uint32_t af[MI][4];
#pragma unroll
            for (int mi = 0; mi < MI; mi++) {
                uint32_t off = (uint32_t)(wm * MT + mi * 16 + a_r) * GPITCH + (kk + a_k) * 2;
                ldmx4(af[mi], aH + off);
            }
#pragma unroll
            for (int nj = 0; nj < NI2; nj++) {
                uint32_t bf[4];
                uint32_t off = (uint32_t)(wn * NT + nj * 16 + b_r) * GPITCH + (kk + b_k) * 2;
                ldmx4(bf, bH + off);
#pragma unroll
                for (int mi = 0; mi < MI; mi++) {
                    mma16816(acc[mi][nj * 2 + 0], af[mi], bf + 0);
                    mma16816(acc[mi][nj * 2 + 1], af[mi], bf + 2);
                }
            }
        }
        CP_WAIT0();
        __syncthreads();
    }

    constexpr int P2 = BN + 4;
    float* tile = (float*)smem;
#pragma unroll
    for (int mi = 0; mi < MI; mi++)
#pragma unroll
        for (int j = 0; j < NI2 * 2; j++) {
            int row = wm * MT + mi * 16 + (lane >> 2);
            int col = wn * NT + j * 8 + (lane & 3) * 2;
            tile[row * P2 + col]           = acc[mi][j][0];
            tile[row * P2 + col + 1]       = acc[mi][j][1];
            tile[(row + 8) * P2 + col]     = acc[mi][j][2];
            tile[(row + 8) * P2 + col + 1] = acc[mi][j][3];
        }
    __syncthreads();

    if (isQ) {
        for (int idx = tid; idx < 128 * BN; idx += GTHREADS) {
            int rr = idx / BN, cc = idx % BN;
            long long grow = bm + rr, gcol = bn + cc;
            qout[grow * HDIM + gcol] =
                __float2half_rn((tile[rr * P2 + cc] + bq[gcol]) * alphaQ);
        }
    } else if (bn >= 768) {
        for (int idx = tid; idx < 128 * BN; idx += GTHREADS) {
            int rr = idx & 127, cc = idx >> 7;
            long long grow = bm + rr;
            long long vcol = bn + cc - 768;
            float val = tile[rr * P2 + cc] + bv[vcol];
            long long b = grow / NKV, t = grow - b * NKV;
            vt[(b * HDIM + vcol) * NKV + t] = __float2half_rn(val);
        }
    } else {
        for (int idx = tid; idx < 128 * BN; idx += GTHREADS) {
            int rr = idx / BN, cc = idx % BN;
            long long grow = bm + rr, gcol = bn + cc;
            kout[grow * (long long)HDIM + gcol] =
                __float2half_rn(tile[rr * P2 + cc] + bk[gcol]);
        }
    }
}

// ======================= fused flash attention ==============================
#define QK_PITCH 144
#define V_PITCH  272
#define KBLK_SZ (128 * QK_PITCH)
#define VBLK_SZ (64 * V_PITCH)
#define FA_SMEM (128 * QK_PITCH + 2 * KBLK_SZ + 2 * VBLK_SZ)

__global__ void __launch_bounds__(256) flash_attn(
    const f16* __restrict__ q, const f16* __restrict__ k,
    const f16* __restrict__ vt, f16* __restrict__ ao)
{
    extern __shared__ char smem[];
    const uint32_t qbase = smem_u32(smem);
    const uint32_t kbase0 = qbase + 128 * QK_PITCH;
    const uint32_t vbase0 = kbase0 + 2 * KBLK_SZ;

    const int tid = threadIdx.x, lane = tid & 31, w = tid >> 5;
    const int z = blockIdx.y;
    const int b = z / NHEADS, h = z % NHEADS;
    const long long bm = (long long)blockIdx.x * 128;

    const f16* gQ = q + ((long long)b * NQ + bm) * HDIM + h * 64;
    const f16* gK = k + (long long)b * NKV * HDIM + h * 64;
    const f16* gV = vt + ((long long)b * HDIM + h * 64) * NKV;

    constexpr int NB = NKV / 128;  // 18

    auto fillKV = [&](int jb) {
        const int s = jb & 1;
        const f16* gKb = gK + (long long)jb * 128 * HDIM;
        uint32_t kb = kbase0 + s * KBLK_SZ;
#pragma unroll
        for (int i = tid; i < 128 * 8; i += 256) {
            int r = i >> 3, c = i & 7;
            cp16(kb + r * QK_PITCH + c * 16, gKb + (long long)r * HDIM + c * 8);
        }
        const f16* gVb = gV + jb * 128;
        uint32_t vb = vbase0 + s * VBLK_SZ;
#pragma unroll
        for (int i = tid; i < 64 * 16; i += 256) {
            int r = i >> 4, c = i & 15;
            cp16(vb + r * V_PITCH + c * 16, gVb + (long long)r * NKV + c * 8);
        }
    };

    for (int i = tid; i < 128 * 8; i += 256) {
        int r = i >> 3, c = i & 7;
        cp16(qbase + r * QK_PITCH + c * 16, gQ + (long long)r * HDIM + c * 8);
    }
    fillKV(0);
    CP_COMMIT();
    fillKV(1);
    CP_COMMIT();
    CP_WAIT1();
    __syncthreads();

    const int a_r = (lane & 7) + ((lane >> 3) & 1) * 8;
    const int a_k = ((lane >> 4) & 1) * 8;
    const int b_r = (lane & 7) + ((lane >> 4) & 1) * 8;
    const int b_k = ((lane >> 3) & 1) * 8;

    uint32_t qf[4][4];
#pragma unroll
    for (int s = 0; s < 4; s++)
        ldmx4(qf[s], qbase + (uint32_t)(16 * w + a_r) * QK_PITCH + (16 * s + a_k) * 2);

    float o[8][4];
#pragma unroll
    for (int i = 0; i < 8; i++)
#pragma unroll
        for (int t = 0; t < 4; t++) o[i][t] = 0.f;
    float m0 = -1e30f, m1 = -1e30f, l0 = 0.f, l1 = 0.f;

    for (int jb = 0; jb < NB; jb++) {
        if (jb > 0) {
            if (jb + 1 < NB) CP_WAIT1(); else CP_WAIT0();
            __syncthreads();
        }
        const uint32_t kb = kbase0 + (jb & 1) * KBLK_SZ;
        const uint32_t vb = vbase0 + (jb & 1) * VBLK_SZ;

        float sacc[16][4];
#pragma unroll
        for (int i = 0; i < 16; i++)
#pragma unroll
            for (int t = 0; t < 4; t++) sacc[i][t] = 0.f;
#pragma unroll
        for (int s = 0; s < 4; s++) {
#pragma unroll
            for (int np = 0; np < 8; np++) {
                uint32_t bf[4];
                ldmx4(bf, kb + (uint32_t)(16 * np + b_r) * QK_PITCH + (16 * s + b_k) * 2);
                mma16816(sacc[2 * np + 0], qf[s], bf + 0);
                mma16816(sacc[2 * np + 1], qf[s], bf + 2);
            }
        }

        float rm0 = -1e30f, rm1 = -1e30f;
#pragma unroll
        for (int i = 0; i < 16; i++) {
            rm0 = fmaxf(rm0, fmaxf(sacc[i][0], sacc[i][1]));
            rm1 = fmaxf(rm1, fmaxf(sacc[i][2], sacc[i][3]));
        }
        rm0 = fmaxf(rm0, __shfl_xor_sync(0xffffffffu, rm0, 1));
        rm0 = fmaxf(rm0, __shfl_xor_sync(0xffffffffu, rm0, 2));
        rm1 = fmaxf(rm1, __shfl_xor_sync(0xffffffffu, rm1, 1));
        rm1 = fmaxf(rm1, __shfl_xor_sync(0xffffffffu, rm1, 2));
        float mn0 = fmaxf(m0, rm0), mn1 = fmaxf(m1, rm1);
        float sc0 = exp2f(m0 - mn0), sc1 = exp2f(m1 - mn1);

        uint32_t pf[16][2];
        float rs0 = 0.f, rs1 = 0.f;
#pragma unroll
        for (int i = 0; i < 16; i++) {
            float e0 = exp2f(sacc[i][0] - mn0);
            float e1 = exp2f(sacc[i][1] - mn0);
            float e2 = exp2f(sacc[i][2] - mn1);
            float e3 = exp2f(sacc[i][3] - mn1);
            rs0 += e0 + e1; rs1 += e2 + e3;
            pf[i][0] = pack_h2(e0, e1);
            pf[i][1] = pack_h2(e2, e3);
        }
        rs0 += __shfl_xor_sync(0xffffffffu, rs0, 1);
        rs0 += __shfl_xor_sync(0xffffffffu, rs0, 2);
        rs1 += __shfl_xor_sync(0xffffffffu, rs1, 1);
        rs1 += __shfl_xor_sync(0xffffffffu, rs1, 2);
        l0 = l0 * sc0 + rs0;
        l1 = l1 * sc1 + rs1;
        m0 = mn0; m1 = mn1;

#pragma unroll
        for (int i = 0; i < 8; i++) {
            o[i][0] *= sc0; o[i][1] *= sc0;
            o[i][2] *= sc1; o[i][3] *= sc1;
        }

#pragma unroll
        for (int s = 0; s < 8; s++) {
            uint32_t af[4] = { pf[2 * s][0], pf[2 * s][1], pf[2 * s + 1][0], pf[2 * s + 1][1] };
#pragma unroll
            for (int np = 0; np < 4; np++) {
                uint32_t bf[4];
                ldmx4(bf, vb + (uint32_t)(16 * np + b_r) * V_PITCH + (16 * s + b_k) * 2);
                mma16816(o[2 * np + 0], af, bf + 0);
                mma16816(o[2 * np + 1], af, bf + 2);
            }
        }
        __syncthreads();
        if (jb + 2 < NB) { fillKV(jb + 2); CP_COMMIT(); }
    }

    float il0 = 1.f / l0, il1 = 1.f / l1;
    const int r = lane >> 2, t2 = (lane & 3) * 2;
    f16* gO = ao + ((long long)b * NQ + bm + 16 * w) * HDIM + h * 64;
#pragma unroll
    for (int nj = 0; nj < 8; nj++) {
        int col = 8 * nj + t2;
        *(uint32_t*)(gO + (long long)r * HDIM + col) =
            pack_h2(o[nj][0] * il0, o[nj][1] * il0);
        *(uint32_t*)(gO + (long long)(r + 8) * HDIM + col) =
            pack_h2(o[nj][2] * il1, o[nj][3] * il1);
    }
}

// -------------------- merged weight transpose + fp16 ------------------------
struct WJobs {
    const float* W[6];
    f16* T[6];
    int N[6], nbx[6], rowOff[6], ldT[6];
    int base[7];
};

__global__ void __launch_bounds__(256) wprep_all(WJobs jb)
{
    __shared__ float s[32][33];
    int bid = blockIdx.x;
    int j = 0;
#pragma unroll
    for (int i = 1; i < 6; i++) if (bid >= jb.base[i]) j = i;
    int lb = bid - jb.base[j];
    const float* W = jb.W[j];
    const int N = jb.N[j];
    int n0 = (lb % jb.nbx[j]) * 32, k0 = (lb / jb.nbx[j]) * 32;
    int tx = threadIdx.x & 31, ty = threadIdx.x >> 5;
#pragma unroll
    for (int jj = 0; jj < 4; jj++)
        s[ty + jj * 8][tx] = W[(long long)(k0 + ty + jj * 8) * N + n0 + tx];
    __syncthreads();
    f16* T = jb.T[j];
    const int ldT = jb.ldT[j], rowOff = jb.rowOff[j];
#pragma unroll
    for (int jj = 0; jj < 4; jj++) {
        int n = n0 + ty + jj * 8, kx = k0 + tx;
        T[(long long)(n + rowOff) * ldT + kx] = __float2half_rn(s[tx][ty + jj * 8]);
    }
}

// -------------------- LayerNorm (merged img + hid) ---------------------------
template <int COLS>
__device__ __forceinline__ void ln_row(
    const float* __restrict__ xr, const float* __restrict__ g,
    const float* __restrict__ b, f16* __restrict__ yr)
{
    constexpr int PT = COLS / 256;
    float v[PT];
    float s = 0.f, s2 = 0.f;
#pragma unroll
    for (int i = 0; i < PT; i++) {
        float t = xr[threadIdx.x + i * 256];
        v[i] = t; s += t; s2 += t * t;
    }
    __shared__ float red0[8], red1[8];
#pragma unroll
    for (int o = 16; o; o >>= 1) {
        s  += __shfl_xor_sync(0xffffffffu, s, o);
        s2 += __shfl_xor_sync(0xffffffffu, s2, o);
    }
    int w = threadIdx.x >> 5, l = threadIdx.x & 31;
    if (l == 0) { red0[w] = s; red1[w] = s2; }
    __syncthreads();
    s  = red0[0] + red0[1] + red0[2] + red0[3] + red0[4] + red0[5] + red0[6] + red0[7];
    s2 = red1[0] + red1[1] + red1[2] + red1[3] + red1[4] + red1[5] + red1[6] + red1[7];

    float mu  = s * (1.f / COLS);
    float var = s2 * (1.f / COLS) - mu * mu;
    float inv = rsqrtf(var + LN_EPS);
#pragma unroll
    for (int i = 0; i < PT; i++) {
        int c = threadIdx.x + i * 256;
        yr[c] = __float2half_rn((v[i] - mu) * inv * g[c] + b[c]);
    }
}

__global__ void __launch_bounds__(256) ln_both(
    const float* __restrict__ x, const float* __restrict__ gimg,
    const float* __restrict__ bimg, f16* __restrict__ xn,
    const float* __restrict__ hs, const float* __restrict__ ghid,
    const float* __restrict__ bhid, f16* __restrict__ hn)
{
    const long long row = blockIdx.x;
    if (row < (long long)BATCH * NKV) {
        ln_row<IMGD>(x + row * IMGD, gimg, bimg, xn + row * IMGD);
    } else {
        const long long r2 = row - (long long)BATCH * NKV;
        ln_row<HDIM>(hs + r2 * HDIM, ghid, bhid, hn + r2 * HDIM);
    }
}

__global__ void __launch_bounds__(256) ln_single(
    const float* __restrict__ x, const float* __restrict__ g,
    const float* __restrict__ b, f16* __restrict__ y)
{
    const long long row = blockIdx.x;
    ln_row<HDIM>(x + row * HDIM, g, b, y + row * HDIM);
}

// -------------------- launch ------------------------------------------------
#define SMEM_GEMM ((2 * (128 + GBN) * GPITCH) > (128 * (GBN + 4) * 4) ? \
                   (2 * (128 + GBN) * GPITCH) : (128 * (GBN + 4) * 4))

extern "C" void kernel_launch(void* const* d_in, const int* in_sizes, int n_in,
                              void* d_out, int out_size)
{
    const float* hs   = (const float*)d_in[0];
    const float* x    = (const float*)d_in[1];
    const float* Wq   = (const float*)d_in[2];
    const float* bq   = (const float*)d_in[3];
    const float* Wk   = (const float*)d_in[4];
    const float* bk   = (const float*)d_in[5];
    const float* Wv   = (const float*)d_in[6];
    const float* bv   = (const float*)d_in[7];
    const float* Wo   = (const float*)d_in[8];
    const float* bo   = (const float*)d_in[9];
    const float* W1   = (const float*)d_in[10];
    const float* b1   = (const float*)d_in[11];
    const float* W2   = (const float*)d_in[12];
    const float* b2   = (const float*)d_in[13];
    const float* gimg = (const float*)d_in[14];
    const float* bimg = (const float*)d_in[15];
    const float* ghid = (const float*)d_in[16];
    const float* bhid = (const float*)d_in[17];
    const float* gffn = (const float*)d_in[18];
    const float* bffn = (const float*)d_in[19];
    float* out = (float*)d_out;

    f16 *xn, *hn, *q, *k, *vt, *ao, *hb, *t1;
    f16 *wq, *wkv, *wo, *w1, *w2;
    float *o2;
    cudaGetSymbolAddress((void**)&xn, g_xn);
    cudaGetSymbolAddress((void**)&hn, g_hn);
    cudaGetSymbolAddress((void**)&q,  g_q);
    cudaGetSymbolAddress((void**)&k,  g_k);
    cudaGetSymbolAddress((void**)&vt, g_vt);
    cudaGetSymbolAddress((void**)&ao, g_ao);
    cudaGetSymbolAddress((void**)&o2, g_o2);
    cudaGetSymbolAddress((void**)&hb, g_hb);
    cudaGetSymbolAddress((void**)&t1, g_t1);
    cudaGetSymbolAddress((void**)&wq, g_wq);
    cudaGetSymbolAddress((void**)&wkv, g_wkv);
    cudaGetSymbolAddress((void**)&wo, g_wo);
    cudaGetSymbolAddress((void**)&w1, g_w1);
    cudaGetSymbolAddress((void**)&w2, g_w2);

    const int SG = SMEM_GEMM;
    cudaFuncSetAttribute(qkv_gemm,    cudaFuncAttributeMaxDynamicSharedMemorySize, SG);
    cudaFuncSetAttribute(mma_gemm<4>, cudaFuncAttributeMaxDynamicSharedMemorySize, SG);
    cudaFuncSetAttribute(mma_gemm<5>, cudaFuncAttributeMaxDynamicSharedMemorySize, SG);
    cudaFuncSetAttribute(flash_attn,  cudaFuncAttributeMaxDynamicSharedMemorySize, FA_SMEM);

    const int MQ = BATCH * NQ;    // 4096

    // 0) merged weight prep
    {
        WJobs jb;
        const float* Ws[6] = { Wq, Wk, Wv, Wo, W1, W2 };
        f16* Ts[6]         = { wq, wkv, wkv, wo, w1, w2 };
        int Ns[6]          = { HDIM, HDIM, HDIM, HDIM, INTER, HDIM };
        int Ks[6]          = { HDIM, IMGD, IMGD, HDIM, HDIM, INTER };
        int ro[6]          = { 0, 0, HDIM, 0, 0, 0 };
        int lt[6]          = { HDIM, IMGD, IMGD, HDIM, HDIM, INTER };
        int total = 0;
        for (int i = 0; i < 6; i++) {
            jb.W[i] = Ws[i]; jb.T[i] = Ts[i]; jb.N[i] = Ns[i];
            jb.nbx[i] = Ns[i] / 32; jb.rowOff[i] = ro[i]; jb.ldT[i] = lt[i];
            jb.base[i] = total;
            total += (Ns[i] / 32) * (Ks[i] / 32);
        }
        jb.base[6] = total;
        wprep_all<<<total, 256>>>(jb);
    }

    // 1) merged LayerNorms -> fp16 (img rows then hid rows)
    ln_both<<<BATCH * NKV + BATCH * NQ, 256>>>(x, gimg, bimg, xn,
                                               hs, ghid, bhid, hn);

    // 2) merged Q + KV projections
    //    y<288: [k|v] = xn @ [Wk|Wv]; y>=288 (x<12): q = (hn@Wq+bq)*scale*log2e
    qkv_gemm<<<dim3((2 * HDIM) / GBN, KV_YBLKS + MQ / 128), GTHREADS, SG>>>(
        xn, wkv, bk, bv, k, vt, hn, wq, bq, q, ATT_SCALE * LOG2E);

    // 3) fused attention: ao = softmax(q k^T) v
    flash_attn<<<dim3(NQ / 128, BATCH * NHEADS), 256, FA_SMEM>>>(q, k, vt, ao);

    // 4) o2 = ao @ Wo + bo + hidden_states  -> fp32
    mma_gemm<4><<<dim3(HDIM / GBN, MQ / 128), GTHREADS, SG>>>(
        ao, wo, bo, hs, o2, nullptr,
        HDIM, HDIM, HDIM, HDIM);

    // 5) hb = LN(o2)
    ln_single<<<BATCH * NQ, 256>>>(o2, gffn, bffn, hb);

    // 6) t1 = gelu(hb @ W1 + b1)
    mma_gemm<5><<<dim3(INTER / GBN, MQ / 128), GTHREADS, SG>>>(
        hb, w1, b1, nullptr, nullptr, t1,
        HDIM, HDIM, HDIM, INTER);

    // 7) out = t1 @ W2 + b2 + o2  -> fp32
    mma_gemm<4><<<dim3(HDIM / GBN, MQ / 128), GTHREADS, SG>>>(
        t1, w2, b2, o2, out, nullptr,
        INTER, INTER, INTER, HDIM);
}